// round 4
// baseline (speedup 1.0000x reference)
#include <cuda_runtime.h>
#include <cstdint>

// ---------------------------------------------------------------------------
// Causal MHA: B=4, S=2048, D=1024, H=16, Dh=64.  fp32 in/out.
// All GEMMs on tensor cores via mma.sync m16n8k8 TF32.
// Projections + QK^T use 3xTF32 split (fp32-grade accuracy); PV single TF32.
// ---------------------------------------------------------------------------

#define DEV_INLINE __device__ __forceinline__

static constexpr int BATCH = 4;
static constexpr int SEQ   = 2048;
static constexpr int DMODEL = 1024;
static constexpr int HEADS = 16;
static constexpr int HDIM  = 64;
static constexpr int MROWS = BATCH * SEQ;          // 8192

// scratch (no cudaMalloc allowed)
__device__ float g_Q[BATCH * HEADS * SEQ * HDIM];   // [b,h,s,dh]
__device__ float g_K[BATCH * HEADS * SEQ * HDIM];
__device__ float g_V[BATCH * HEADS * SEQ * HDIM];
__device__ float g_AO[MROWS * DMODEL];              // attention out, [b,s,h*64+dh]

DEV_INLINE unsigned f2tf(float x) {
    unsigned u;
    asm("cvt.rna.tf32.f32 %0, %1;" : "=r"(u) : "f"(x));
    return u;
}
DEV_INLINE unsigned fu(float x) { return __float_as_uint(x); }

DEV_INLINE void mma8(float* d,
                     unsigned a0, unsigned a1, unsigned a2, unsigned a3,
                     unsigned b0, unsigned b1) {
    asm volatile(
        "mma.sync.aligned.m16n8k8.row.col.f32.tf32.tf32.f32 "
        "{%0,%1,%2,%3},{%4,%5,%6,%7},{%8,%9},{%0,%1,%2,%3};\n"
        : "+f"(d[0]), "+f"(d[1]), "+f"(d[2]), "+f"(d[3])
        : "r"(a0), "r"(a1), "r"(a2), "r"(a3), "r"(b0), "r"(b1));
}

// ---------------------------------------------------------------------------
// Projection GEMM:  out[m][n] = sum_k A[m][k] * W[n][k]
// M=8192, N=1024, K=1024.  CTA tile 128x64, BK=32, 8 warps (4x2), 3xTF32.
// head_layout=1: write to [b,h,s,dh] scratch.  head_layout=0: plain [m][n].
// ---------------------------------------------------------------------------
static constexpr int P_BM = 128;
static constexpr int P_BN = 64;
static constexpr int P_BK = 32;
static constexpr int P_PA = 36;   // smem pitch (floats), conflict-free frags
static constexpr int P_PB = 36;
static constexpr int PROJ_SMEM_FLOATS = 2 * P_BM * P_PA + 2 * P_BN * P_PB;
static constexpr int PROJ_SMEM_BYTES  = PROJ_SMEM_FLOATS * 4;

__global__ __launch_bounds__(256, 2)
void proj_kernel(const float* __restrict__ A, const float* __restrict__ W,
                 float* __restrict__ dst, int head_layout) {
    extern __shared__ float sm[];
    float* Ah = sm;
    float* Al = Ah + P_BM * P_PA;
    float* Bh = Al + P_BM * P_PA;
    float* Bl = Bh + P_BN * P_PB;

    const int m0 = blockIdx.x * P_BM;
    const int n0 = blockIdx.y * P_BN;
    const int tid  = threadIdx.x;
    const int warp = tid >> 5;
    const int lane = tid & 31;
    const int wm = warp & 3;   // 0..3  (32 rows each)
    const int wn = warp >> 2;  // 0..1  (32 cols each)

    float acc[2][4][4];
#pragma unroll
    for (int mi = 0; mi < 2; mi++)
#pragma unroll
        for (int ni = 0; ni < 4; ni++)
#pragma unroll
            for (int j = 0; j < 4; j++) acc[mi][ni][j] = 0.0f;

    float4 aReg[4], bReg[2];

    auto loadG = [&](int k0) {
#pragma unroll
        for (int i = 0; i < 4; i++) {
            int idx = tid + i * 256;          // < 1024
            int r = idx >> 3, c = (idx & 7) << 2;
            aReg[i] = *reinterpret_cast<const float4*>(&A[(size_t)(m0 + r) * DMODEL + k0 + c]);
        }
#pragma unroll
        for (int i = 0; i < 2; i++) {
            int idx = tid + i * 256;          // < 512
            int r = idx >> 3, c = (idx & 7) << 2;
            bReg[i] = *reinterpret_cast<const float4*>(&W[(size_t)(n0 + r) * DMODEL + k0 + c]);
        }
    };
    auto storeStage = [&]() {
#pragma unroll
        for (int i = 0; i < 4; i++) {
            int idx = tid + i * 256;
            int r = idx >> 3, c = (idx & 7) << 2;
            float v[4] = {aReg[i].x, aReg[i].y, aReg[i].z, aReg[i].w};
#pragma unroll
            for (int j = 0; j < 4; j++) {
                float hi = __uint_as_float(f2tf(v[j]));
                Ah[r * P_PA + c + j] = hi;
                Al[r * P_PA + c + j] = __uint_as_float(f2tf(v[j] - hi));
            }
        }
#pragma unroll
        for (int i = 0; i < 2; i++) {
            int idx = tid + i * 256;
            int r = idx >> 3, c = (idx & 7) << 2;
            float v[4] = {bReg[i].x, bReg[i].y, bReg[i].z, bReg[i].w};
#pragma unroll
            for (int j = 0; j < 4; j++) {
                float hi = __uint_as_float(f2tf(v[j]));
                Bh[r * P_PB + c + j] = hi;
                Bl[r * P_PB + c + j] = __uint_as_float(f2tf(v[j] - hi));
            }
        }
    };

    loadG(0);
    storeStage();
    __syncthreads();

    for (int k0 = 0; k0 < DMODEL; k0 += P_BK) {
        const bool has_next = (k0 + P_BK) < DMODEL;
        if (has_next) loadG(k0 + P_BK);

#pragma unroll
        for (int kk = 0; kk < 4; kk++) {
            unsigned ah[2][4], al[2][4];
#pragma unroll
            for (int mi = 0; mi < 2; mi++) {
                int row = wm * 32 + mi * 16 + (lane >> 2);
                int base = row * P_PA + kk * 8 + (lane & 3);
                ah[mi][0] = fu(Ah[base]);
                ah[mi][1] = fu(Ah[base + 8 * P_PA]);
                ah[mi][2] = fu(Ah[base + 4]);
                ah[mi][3] = fu(Ah[base + 8 * P_PA + 4]);
                al[mi][0] = fu(Al[base]);
                al[mi][1] = fu(Al[base + 8 * P_PA]);
                al[mi][2] = fu(Al[base + 4]);
                al[mi][3] = fu(Al[base + 8 * P_PA + 4]);
            }
#pragma unroll
            for (int ni = 0; ni < 4; ni++) {
                int colb = wn * 32 + ni * 8 + (lane >> 2);
                int bb = colb * P_PB + kk * 8 + (lane & 3);
                unsigned bh0 = fu(Bh[bb]), bh1 = fu(Bh[bb + 4]);
                unsigned bl0 = fu(Bl[bb]), bl1 = fu(Bl[bb + 4]);
#pragma unroll
                for (int mi = 0; mi < 2; mi++) {
                    mma8(acc[mi][ni], ah[mi][0], ah[mi][1], ah[mi][2], ah[mi][3], bh0, bh1);
                    mma8(acc[mi][ni], al[mi][0], al[mi][1], al[mi][2], al[mi][3], bh0, bh1);
                    mma8(acc[mi][ni], ah[mi][0], ah[mi][1], ah[mi][2], ah[mi][3], bl0, bl1);
                }
            }
        }
        __syncthreads();
        if (has_next) {
            storeStage();
        }
        __syncthreads();
    }

    // epilogue
#pragma unroll
    for (int mi = 0; mi < 2; mi++) {
#pragma unroll
        for (int ni = 0; ni < 4; ni++) {
            int r0 = m0 + wm * 32 + mi * 16 + (lane >> 2);
            int r1 = r0 + 8;
            int c0 = n0 + wn * 32 + ni * 8 + 2 * (lane & 3);
            int c1 = c0 + 1;
#pragma unroll
            for (int e = 0; e < 4; e++) {
                int r = (e < 2) ? r0 : r1;
                int c = (e & 1) ? c1 : c0;
                float v = acc[mi][ni][e];
                if (head_layout) {
                    int b = r >> 11, s = r & 2047;
                    int h = c >> 6, dh = c & 63;
                    dst[(((size_t)(b * HEADS + h)) * SEQ + s) * HDIM + dh] = v;
                } else {
                    dst[(size_t)r * DMODEL + c] = v;
                }
            }
        }
    }
}

// ---------------------------------------------------------------------------
// Flash attention: CTA = (qtile of 64 rows, head, batch). 4 warps.
// S = Q K^T (3xTF32), online softmax, O += P V (TF32).
// Causal: only kv tiles j <= qt; diagonal tile masked.
// ---------------------------------------------------------------------------
static constexpr int A_PQ = 68;   // pitch for Q/K/P tiles
static constexpr int A_PV = 72;   // pitch for V tile (conflict-free B-frags)
static constexpr int ATTN_SMEM_FLOATS = 4 * 64 * A_PQ + 64 * A_PV + 64 * A_PQ;
static constexpr int ATTN_SMEM_BYTES  = ATTN_SMEM_FLOATS * 4;

__global__ __launch_bounds__(128, 2)
void attn_kernel(const float* __restrict__ Q, const float* __restrict__ K,
                 const float* __restrict__ V, float* __restrict__ out) {
    extern __shared__ float sm[];
    float* Qh = sm;
    float* Ql = Qh + 64 * A_PQ;
    float* Kh = Ql + 64 * A_PQ;
    float* Kl = Kh + 64 * A_PQ;
    float* Vs = Kl + 64 * A_PQ;
    float* Ps = Vs + 64 * A_PV;

    const int qt = (int)(gridDim.x - 1) - (int)blockIdx.x;  // heavy tiles first
    const int h = blockIdx.y;
    const int b = blockIdx.z;
    const int bh = b * HEADS + h;
    const int q0 = qt * 64;

    const float* Qb = Q + (size_t)bh * SEQ * HDIM;
    const float* Kb = K + (size_t)bh * SEQ * HDIM;
    const float* Vb = V + (size_t)bh * SEQ * HDIM;

    const int tid = threadIdx.x;
    const int warp = tid >> 5;
    const int lane = tid & 31;

    // load Q tile (scaled by 1/sqrt(64) = 0.125, exact) and split
#pragma unroll
    for (int i = 0; i < 8; i++) {
        int idx = tid + i * 128;          // < 1024 float4
        int r = idx >> 4, c = (idx & 15) << 2;
        float4 q4 = *reinterpret_cast<const float4*>(&Qb[(size_t)(q0 + r) * HDIM + c]);
        float v[4] = {q4.x, q4.y, q4.z, q4.w};
#pragma unroll
        for (int j = 0; j < 4; j++) {
            float x = v[j] * 0.125f;
            float hi = __uint_as_float(f2tf(x));
            Qh[r * A_PQ + c + j] = hi;
            Ql[r * A_PQ + c + j] = __uint_as_float(f2tf(x - hi));
        }
    }

    const float NEG = -1e30f;
    float mr0 = NEG, mr1 = NEG, l0 = 0.0f, l1 = 0.0f;
    float o[8][4];
#pragma unroll
    for (int nc = 0; nc < 8; nc++)
#pragma unroll
        for (int j = 0; j < 4; j++) o[nc][j] = 0.0f;

    for (int j = 0; j <= qt; j++) {
        __syncthreads();   // prior PV done reading Vs/Ps; Q tile stored (j==0)
        // load K tile (split) and V tile (rna-rounded)
#pragma unroll
        for (int i = 0; i < 8; i++) {
            int idx = tid + i * 128;
            int r = idx >> 4, c = (idx & 15) << 2;
            float4 k4 = *reinterpret_cast<const float4*>(&Kb[(size_t)(j * 64 + r) * HDIM + c]);
            float4 v4 = *reinterpret_cast<const float4*>(&Vb[(size_t)(j * 64 + r) * HDIM + c]);
            float kv[4] = {k4.x, k4.y, k4.z, k4.w};
            float vv[4] = {v4.x, v4.y, v4.z, v4.w};
#pragma unroll
            for (int t = 0; t < 4; t++) {
                float hi = __uint_as_float(f2tf(kv[t]));
                Kh[r * A_PQ + c + t] = hi;
                Kl[r * A_PQ + c + t] = __uint_as_float(f2tf(kv[t] - hi));
                Vs[r * A_PV + c + t] = __uint_as_float(f2tf(vv[t]));
            }
        }
        __syncthreads();

        // S = Q K^T  (16 rows per warp x 64 cols), 3xTF32
        float s[8][4];
#pragma unroll
        for (int nc = 0; nc < 8; nc++)
#pragma unroll
            for (int e = 0; e < 4; e++) s[nc][e] = 0.0f;

#pragma unroll
        for (int kk = 0; kk < 8; kk++) {
            int ab = (16 * warp + (lane >> 2)) * A_PQ + kk * 8 + (lane & 3);
            unsigned qh0 = fu(Qh[ab]), qh1 = fu(Qh[ab + 8 * A_PQ]);
            unsigned qh2 = fu(Qh[ab + 4]), qh3 = fu(Qh[ab + 8 * A_PQ + 4]);
            unsigned ql0 = fu(Ql[ab]), ql1 = fu(Ql[ab + 8 * A_PQ]);
            unsigned ql2 = fu(Ql[ab + 4]), ql3 = fu(Ql[ab + 8 * A_PQ + 4]);
#pragma unroll
            for (int nc = 0; nc < 8; nc++) {
                int bb = (nc * 8 + (lane >> 2)) * A_PQ + kk * 8 + (lane & 3);
                unsigned kh0 = fu(Kh[bb]), kh1 = fu(Kh[bb + 4]);
                unsigned kl0 = fu(Kl[bb]), kl1 = fu(Kl[bb + 4]);
                mma8(s[nc], qh0, qh1, qh2, qh3, kh0, kh1);
                mma8(s[nc], ql0, ql1, ql2, ql3, kh0, kh1);
                mma8(s[nc], qh0, qh1, qh2, qh3, kl0, kl1);
            }
        }

        // causal mask on diagonal tile
        if (j == qt) {
            int r0 = 16 * warp + (lane >> 2), r1 = r0 + 8;
#pragma unroll
            for (int nc = 0; nc < 8; nc++) {
                int c0 = nc * 8 + 2 * (lane & 3), c1 = c0 + 1;
                if (c0 > r0) s[nc][0] = NEG;
                if (c1 > r0) s[nc][1] = NEG;
                if (c0 > r1) s[nc][2] = NEG;
                if (c1 > r1) s[nc][3] = NEG;
            }
        }

        // online softmax
        float pm0 = NEG, pm1 = NEG;
#pragma unroll
        for (int nc = 0; nc < 8; nc++) {
            pm0 = fmaxf(pm0, fmaxf(s[nc][0], s[nc][1]));
            pm1 = fmaxf(pm1, fmaxf(s[nc][2], s[nc][3]));
        }
        pm0 = fmaxf(pm0, __shfl_xor_sync(0xffffffffu, pm0, 1));
        pm0 = fmaxf(pm0, __shfl_xor_sync(0xffffffffu, pm0, 2));
        pm1 = fmaxf(pm1, __shfl_xor_sync(0xffffffffu, pm1, 1));
        pm1 = fmaxf(pm1, __shfl_xor_sync(0xffffffffu, pm1, 2));

        float mn0 = fmaxf(mr0, pm0), mn1 = fmaxf(mr1, pm1);
        float al0 = __expf(mr0 - mn0), al1 = __expf(mr1 - mn1);
        l0 *= al0;
        l1 *= al1;

        float rs0 = 0.0f, rs1 = 0.0f;
        int pr0 = 16 * warp + (lane >> 2);
#pragma unroll
        for (int nc = 0; nc < 8; nc++) {
            float p0 = __expf(s[nc][0] - mn0);
            float p1 = __expf(s[nc][1] - mn0);
            float p2 = __expf(s[nc][2] - mn1);
            float p3 = __expf(s[nc][3] - mn1);
            rs0 += p0 + p1;
            rs1 += p2 + p3;
            o[nc][0] *= al0; o[nc][1] *= al0;
            o[nc][2] *= al1; o[nc][3] *= al1;
            int c0 = nc * 8 + 2 * (lane & 3);
            Ps[pr0 * A_PQ + c0]           = __uint_as_float(f2tf(p0));
            Ps[pr0 * A_PQ + c0 + 1]       = __uint_as_float(f2tf(p1));
            Ps[(pr0 + 8) * A_PQ + c0]     = __uint_as_float(f2tf(p2));
            Ps[(pr0 + 8) * A_PQ + c0 + 1] = __uint_as_float(f2tf(p3));
        }
        rs0 += __shfl_xor_sync(0xffffffffu, rs0, 1);
        rs0 += __shfl_xor_sync(0xffffffffu, rs0, 2);
        rs1 += __shfl_xor_sync(0xffffffffu, rs1, 1);
        rs1 += __shfl_xor_sync(0xffffffffu, rs1, 2);
        l0 += rs0;
        l1 += rs1;
        mr0 = mn0;
        mr1 = mn1;
        __syncwarp();   // P writes visible across lanes of this warp

        // O += P V
#pragma unroll
        for (int kk = 0; kk < 8; kk++) {
            int pb = (16 * warp + (lane >> 2)) * A_PQ + kk * 8 + (lane & 3);
            unsigned pa0 = fu(Ps[pb]), pa1 = fu(Ps[pb + 8 * A_PQ]);
            unsigned pa2 = fu(Ps[pb + 4]), pa3 = fu(Ps[pb + 8 * A_PQ + 4]);
#pragma unroll
            for (int nc = 0; nc < 8; nc++) {
                int vb = (kk * 8 + (lane & 3)) * A_PV + nc * 8 + (lane >> 2);
                unsigned v0 = fu(Vs[vb]), v1 = fu(Vs[vb + 4 * A_PV]);
                mma8(o[nc], pa0, pa1, pa2, pa3, v0, v1);
            }
        }
    }

    // epilogue: normalize, write to [b, s, h*64+dh]
    float inv0 = 1.0f / l0, inv1 = 1.0f / l1;
    int r0g = q0 + 16 * warp + (lane >> 2);
    int r1g = r0g + 8;
#pragma unroll
    for (int nc = 0; nc < 8; nc++) {
        int col = h * HDIM + nc * 8 + 2 * (lane & 3);
        size_t b0 = ((size_t)(b * SEQ + r0g)) * DMODEL + col;
        size_t b1 = ((size_t)(b * SEQ + r1g)) * DMODEL + col;
        out[b0]     = o[nc][0] * inv0;
        out[b0 + 1] = o[nc][1] * inv0;
        out[b1]     = o[nc][2] * inv1;
        out[b1 + 1] = o[nc][3] * inv1;
    }
}

// ---------------------------------------------------------------------------
extern "C" void kernel_launch(void* const* d_in, const int* in_sizes, int n_in,
                              void* d_out, int out_size) {
    const float* x  = (const float*)d_in[0];
    const float* wq = (const float*)d_in[1];
    const float* wk = (const float*)d_in[2];
    const float* wv = (const float*)d_in[3];
    const float* wo = (const float*)d_in[4];

    float *gq, *gk, *gv, *gao;
    cudaGetSymbolAddress((void**)&gq, g_Q);
    cudaGetSymbolAddress((void**)&gk, g_K);
    cudaGetSymbolAddress((void**)&gv, g_V);
    cudaGetSymbolAddress((void**)&gao, g_AO);

    cudaFuncSetAttribute(proj_kernel, cudaFuncAttributeMaxDynamicSharedMemorySize,
                         PROJ_SMEM_BYTES);
    cudaFuncSetAttribute(attn_kernel, cudaFuncAttributeMaxDynamicSharedMemorySize,
                         ATTN_SMEM_BYTES);

    dim3 pgrid(MROWS / P_BM, DMODEL / P_BN);   // (64, 16)
    proj_kernel<<<pgrid, 256, PROJ_SMEM_BYTES>>>(x, wq, gq, 1);
    proj_kernel<<<pgrid, 256, PROJ_SMEM_BYTES>>>(x, wk, gk, 1);
    proj_kernel<<<pgrid, 256, PROJ_SMEM_BYTES>>>(x, wv, gv, 1);

    dim3 agrid(SEQ / 64, HEADS, BATCH);        // (32, 16, 4)
    attn_kernel<<<agrid, 128, ATTN_SMEM_BYTES>>>(gq, gk, gv, gao);

    proj_kernel<<<pgrid, 256, PROJ_SMEM_BYTES>>>(gao, wo, (float*)d_out, 0);
}

// round 7
// speedup vs baseline: 1.8481x; 1.8481x over previous
#include <cuda_runtime.h>
#include <cuda_bf16.h>
#include <cstdint>

// ---------------------------------------------------------------------------
// Causal MHA: B=4, S=2048, D=1024, H=16, Dh=64.  fp32 in/out.
// Projections + QK^T: bf16x3 split on mma.m16n8k16 (fp32-grade accuracy).
// PV: single TF32 m16n8k8 (known-good from prior round).
// ---------------------------------------------------------------------------

#define DEV_INLINE __device__ __forceinline__

static constexpr int BATCH = 4;
static constexpr int SEQ   = 2048;
static constexpr int DMODEL = 1024;
static constexpr int HEADS = 16;
static constexpr int HDIM  = 64;
static constexpr int MROWS = BATCH * SEQ;          // 8192

__device__ float g_Q[BATCH * HEADS * SEQ * HDIM];
__device__ float g_K[BATCH * HEADS * SEQ * HDIM];
__device__ float g_V[BATCH * HEADS * SEQ * HDIM];
__device__ float g_AO[MROWS * DMODEL];

DEV_INLINE unsigned f2tf(float x) {
    unsigned u;
    asm("cvt.rna.tf32.f32 %0, %1;" : "=r"(u) : "f"(x));
    return u;
}
DEV_INLINE unsigned fu(float x) { return __float_as_uint(x); }

// pack two floats to bf16x2: x0 -> low half (first k), x1 -> high half
DEV_INLINE unsigned pack2(float x0, float x1) {
    unsigned r;
    asm("cvt.rn.bf16x2.f32 %0, %1, %2;" : "=r"(r) : "f"(x1), "f"(x0));
    return r;
}
DEV_INLINE unsigned cvta_s(const void* p) {
    return (unsigned)__cvta_generic_to_shared(p);
}
DEV_INLINE void ldsm4(unsigned& r0, unsigned& r1, unsigned& r2, unsigned& r3,
                      unsigned addr) {
    asm volatile("ldmatrix.sync.aligned.m8n8.x4.shared.b16 {%0,%1,%2,%3}, [%4];"
                 : "=r"(r0), "=r"(r1), "=r"(r2), "=r"(r3) : "r"(addr));
}

// tf32 m16n8k8 (PV path)
DEV_INLINE void mma8(float* d,
                     unsigned a0, unsigned a1, unsigned a2, unsigned a3,
                     unsigned b0, unsigned b1) {
    asm volatile(
        "mma.sync.aligned.m16n8k8.row.col.f32.tf32.tf32.f32 "
        "{%0,%1,%2,%3},{%4,%5,%6,%7},{%8,%9},{%0,%1,%2,%3};\n"
        : "+f"(d[0]), "+f"(d[1]), "+f"(d[2]), "+f"(d[3])
        : "r"(a0), "r"(a1), "r"(a2), "r"(a3), "r"(b0), "r"(b1));
}

// bf16 m16n8k16
DEV_INLINE void mma16(float* d,
                      unsigned a0, unsigned a1, unsigned a2, unsigned a3,
                      unsigned b0, unsigned b1) {
    asm volatile(
        "mma.sync.aligned.m16n8k16.row.col.f32.bf16.bf16.f32 "
        "{%0,%1,%2,%3},{%4,%5,%6,%7},{%8,%9},{%0,%1,%2,%3};\n"
        : "+f"(d[0]), "+f"(d[1]), "+f"(d[2]), "+f"(d[3])
        : "r"(a0), "r"(a1), "r"(a2), "r"(a3), "r"(b0), "r"(b1));
}

// split 2 floats into hi/lo bf16x2 words
DEV_INLINE void split_pack(float x0, float x1, unsigned& wh, unsigned& wl) {
    wh = pack2(x0, x1);
    float h0 = __uint_as_float(wh << 16);
    float h1 = __uint_as_float(wh & 0xffff0000u);
    wl = pack2(x0 - h0, x1 - h1);
}

// ---------------------------------------------------------------------------
// Projection GEMM: out[m][n] = sum_k A[m][k] * W[n][k]
// M=8192, N=1024, K=1024. CTA 128x64, BK=32, 8 warps (4x2), bf16x3 k16.
// smem pitch 20 words (bf16x2) per row -> conflict-free ldmatrix.
// ---------------------------------------------------------------------------
static constexpr int P_BM = 128;
static constexpr int P_BN = 64;
static constexpr int P_BK = 32;
static constexpr int P_PW = 20;                          // words per row
static constexpr int PROJ_SMEM_WORDS = (2 * P_BM + 2 * P_BN) * P_PW;  // 7680
static constexpr int PROJ_SMEM_BYTES = PROJ_SMEM_WORDS * 4;           // 30720

__global__ __launch_bounds__(256, 2)
void proj_kernel(const float* __restrict__ A, const float* __restrict__ W,
                 float* __restrict__ dst, int head_layout) {
    extern __shared__ unsigned smw[];
    unsigned* Ah = smw;
    unsigned* Al = Ah + P_BM * P_PW;
    unsigned* Bh = Al + P_BM * P_PW;
    unsigned* Bl = Bh + P_BN * P_PW;

    const int m0 = blockIdx.x * P_BM;
    const int n0 = blockIdx.y * P_BN;
    const int tid  = threadIdx.x;
    const int warp = tid >> 5;
    const int lane = tid & 31;
    const int wm = warp & 3;   // 0..3  (32 rows)
    const int wn = warp >> 2;  // 0..1  (32 cols)

    // ldmatrix lane offsets
    const int a_row_off  = (lane & 7) + ((lane >> 3) & 1) * 8;
    const int a_word_off = ((lane >> 4) & 1) * 4;
    const int b_row_off  = (lane & 7) + ((lane >> 4) & 1) * 8;
    const int b_word_off = ((lane >> 3) & 1) * 4;

    const unsigned AhB = cvta_s(Ah), AlB = cvta_s(Al);
    const unsigned BhB = cvta_s(Bh), BlB = cvta_s(Bl);

    // per-lane base addresses (bytes), kk adds 32 bytes
    unsigned aAddr[2], bAddr[2];
#pragma unroll
    for (int mi = 0; mi < 2; mi++)
        aAddr[mi] = ((wm * 32 + mi * 16 + a_row_off) * P_PW + a_word_off) * 4u;
#pragma unroll
    for (int p = 0; p < 2; p++)
        bAddr[p] = ((wn * 32 + p * 16 + b_row_off) * P_PW + b_word_off) * 4u;

    float acc[2][4][4];
#pragma unroll
    for (int mi = 0; mi < 2; mi++)
#pragma unroll
        for (int ni = 0; ni < 4; ni++)
#pragma unroll
            for (int j = 0; j < 4; j++) acc[mi][ni][j] = 0.0f;

    float4 aReg[4], bReg[2];

    auto loadG = [&](int k0) {
#pragma unroll
        for (int i = 0; i < 4; i++) {
            int idx = tid + i * 256;          // < 1024
            int r = idx >> 3, c = (idx & 7) << 2;
            aReg[i] = *reinterpret_cast<const float4*>(&A[(size_t)(m0 + r) * DMODEL + k0 + c]);
        }
#pragma unroll
        for (int i = 0; i < 2; i++) {
            int idx = tid + i * 256;          // < 512
            int r = idx >> 3, c = (idx & 7) << 2;
            bReg[i] = *reinterpret_cast<const float4*>(&W[(size_t)(n0 + r) * DMODEL + k0 + c]);
        }
    };
    auto storeStage = [&]() {
#pragma unroll
        for (int i = 0; i < 4; i++) {
            int idx = tid + i * 256;
            int r = idx >> 3, w = (idx & 7) * 2;   // word pair start
            unsigned wh0, wl0, wh1, wl1;
            split_pack(aReg[i].x, aReg[i].y, wh0, wl0);
            split_pack(aReg[i].z, aReg[i].w, wh1, wl1);
            Ah[r * P_PW + w] = wh0; Ah[r * P_PW + w + 1] = wh1;
            Al[r * P_PW + w] = wl0; Al[r * P_PW + w + 1] = wl1;
        }
#pragma unroll
        for (int i = 0; i < 2; i++) {
            int idx = tid + i * 256;
            int r = idx >> 3, w = (idx & 7) * 2;
            unsigned wh0, wl0, wh1, wl1;
            split_pack(bReg[i].x, bReg[i].y, wh0, wl0);
            split_pack(bReg[i].z, bReg[i].w, wh1, wl1);
            Bh[r * P_PW + w] = wh0; Bh[r * P_PW + w + 1] = wh1;
            Bl[r * P_PW + w] = wl0; Bl[r * P_PW + w + 1] = wl1;
        }
    };

    loadG(0);
    storeStage();
    __syncthreads();

    for (int k0 = 0; k0 < DMODEL; k0 += P_BK) {
        const bool has_next = (k0 + P_BK) < DMODEL;
        if (has_next) loadG(k0 + P_BK);

#pragma unroll
        for (int kk = 0; kk < 2; kk++) {            // two k16 chunks
            unsigned ah[2][4], al[2][4];
#pragma unroll
            for (int mi = 0; mi < 2; mi++) {
                ldsm4(ah[mi][0], ah[mi][1], ah[mi][2], ah[mi][3],
                      AhB + aAddr[mi] + kk * 32u);
                ldsm4(al[mi][0], al[mi][1], al[mi][2], al[mi][3],
                      AlB + aAddr[mi] + kk * 32u);
            }
#pragma unroll
            for (int p = 0; p < 2; p++) {
                unsigned bh0, bh1, bh2, bh3, bl0, bl1, bl2, bl3;
                ldsm4(bh0, bh1, bh2, bh3, BhB + bAddr[p] + kk * 32u);
                ldsm4(bl0, bl1, bl2, bl3, BlB + bAddr[p] + kk * 32u);
#pragma unroll
                for (int mi = 0; mi < 2; mi++) {
                    // ni = 2p: regs (bh0,bh1); ni = 2p+1: regs (bh2,bh3)
                    mma16(acc[mi][2 * p],     ah[mi][0], ah[mi][1], ah[mi][2], ah[mi][3], bh0, bh1);
                    mma16(acc[mi][2 * p],     al[mi][0], al[mi][1], al[mi][2], al[mi][3], bh0, bh1);
                    mma16(acc[mi][2 * p],     ah[mi][0], ah[mi][1], ah[mi][2], ah[mi][3], bl0, bl1);
                    mma16(acc[mi][2 * p + 1], ah[mi][0], ah[mi][1], ah[mi][2], ah[mi][3], bh2, bh3);
                    mma16(acc[mi][2 * p + 1], al[mi][0], al[mi][1], al[mi][2], al[mi][3], bh2, bh3);
                    mma16(acc[mi][2 * p + 1], ah[mi][0], ah[mi][1], ah[mi][2], ah[mi][3], bl2, bl3);
                }
            }
        }
        __syncthreads();
        if (has_next) storeStage();
        __syncthreads();
    }

    // epilogue (acc layout identical to tf32 version)
#pragma unroll
    for (int mi = 0; mi < 2; mi++) {
#pragma unroll
        for (int ni = 0; ni < 4; ni++) {
            int r0 = m0 + wm * 32 + mi * 16 + (lane >> 2);
            int r1 = r0 + 8;
            int c0 = n0 + wn * 32 + ni * 8 + 2 * (lane & 3);
            int c1 = c0 + 1;
#pragma unroll
            for (int e = 0; e < 4; e++) {
                int r = (e < 2) ? r0 : r1;
                int c = (e & 1) ? c1 : c0;
                float v = acc[mi][ni][e];
                if (head_layout) {
                    int b = r >> 11, s = r & 2047;
                    int h = c >> 6, dh = c & 63;
                    dst[(((size_t)(b * HEADS + h)) * SEQ + s) * HDIM + dh] = v;
                } else {
                    dst[(size_t)r * DMODEL + c] = v;
                }
            }
        }
    }
}

// ---------------------------------------------------------------------------
// Flash attention: CTA = (64-row q tile, head, batch), 4 warps.
// S = Q K^T with bf16x3 k16; online softmax; O += P V with TF32 k8.
// ---------------------------------------------------------------------------
static constexpr int A_PW = 36;   // bf16x2 word pitch for Q/K tiles (conflict-free)
static constexpr int A_PV = 72;   // fp32 pitch for V tile
static constexpr int A_PQ = 68;   // fp32 pitch for P tile
// words: Qh/Ql/Kh/Kl = 4*64*36 = 9216; Vs = 64*72 = 4608 f; Ps = 64*68 = 4352 f
static constexpr int ATTN_SMEM_FLOATS = 4 * 64 * A_PW + 64 * A_PV + 64 * A_PQ; // 18176
static constexpr int ATTN_SMEM_BYTES  = ATTN_SMEM_FLOATS * 4;                  // 72704

__global__ __launch_bounds__(128, 3)
void attn_kernel(const float* __restrict__ Q, const float* __restrict__ K,
                 const float* __restrict__ V, float* __restrict__ out) {
    extern __shared__ float sm[];
    unsigned* Qh = reinterpret_cast<unsigned*>(sm);
    unsigned* Ql = Qh + 64 * A_PW;
    unsigned* Kh = Ql + 64 * A_PW;
    unsigned* Kl = Kh + 64 * A_PW;
    float* Vs = sm + 4 * 64 * A_PW;
    float* Ps = Vs + 64 * A_PV;

    const int qt = (int)(gridDim.x - 1) - (int)blockIdx.x;  // heavy tiles first
    const int h = blockIdx.y;
    const int b = blockIdx.z;
    const int bh = b * HEADS + h;
    const int q0 = qt * 64;

    const float* Qb = Q + (size_t)bh * SEQ * HDIM;
    const float* Kb = K + (size_t)bh * SEQ * HDIM;
    const float* Vb = V + (size_t)bh * SEQ * HDIM;

    const int tid = threadIdx.x;
    const int warp = tid >> 5;
    const int lane = tid & 31;

    const int a_row_off  = (lane & 7) + ((lane >> 3) & 1) * 8;
    const int a_word_off = ((lane >> 4) & 1) * 4;
    const int b_row_off  = (lane & 7) + ((lane >> 4) & 1) * 8;
    const int b_word_off = ((lane >> 3) & 1) * 4;

    const unsigned QhB = cvta_s(Qh), QlB = cvta_s(Ql);
    const unsigned KhB = cvta_s(Kh), KlB = cvta_s(Kl);
    const unsigned qAddr = ((16 * warp + a_row_off) * A_PW + a_word_off) * 4u;
    unsigned kAddr[4];
#pragma unroll
    for (int p = 0; p < 4; p++)
        kAddr[p] = ((p * 16 + b_row_off) * A_PW + b_word_off) * 4u;

    // load Q tile (scaled by 0.125) and split to bf16 hi/lo
#pragma unroll
    for (int i = 0; i < 8; i++) {
        int idx = tid + i * 128;          // < 1024 float4
        int r = idx >> 4, c4 = idx & 15;
        float4 q4 = *reinterpret_cast<const float4*>(&Qb[(size_t)(q0 + r) * HDIM + c4 * 4]);
        unsigned wh0, wl0, wh1, wl1;
        split_pack(q4.x * 0.125f, q4.y * 0.125f, wh0, wl0);
        split_pack(q4.z * 0.125f, q4.w * 0.125f, wh1, wl1);
        Qh[r * A_PW + c4 * 2] = wh0; Qh[r * A_PW + c4 * 2 + 1] = wh1;
        Ql[r * A_PW + c4 * 2] = wl0; Ql[r * A_PW + c4 * 2 + 1] = wl1;
    }

    const float NEG = -1e30f;
    float mr0 = NEG, mr1 = NEG, l0 = 0.0f, l1 = 0.0f;
    float o[8][4];
#pragma unroll
    for (int nc = 0; nc < 8; nc++)
#pragma unroll
        for (int j = 0; j < 4; j++) o[nc][j] = 0.0f;

    for (int j = 0; j <= qt; j++) {
        __syncthreads();
        // load K tile (bf16 split) and V tile (tf32 fp32)
#pragma unroll
        for (int i = 0; i < 8; i++) {
            int idx = tid + i * 128;
            int r = idx >> 4, c4 = idx & 15;
            float4 k4 = *reinterpret_cast<const float4*>(&Kb[(size_t)(j * 64 + r) * HDIM + c4 * 4]);
            float4 v4 = *reinterpret_cast<const float4*>(&Vb[(size_t)(j * 64 + r) * HDIM + c4 * 4]);
            unsigned wh0, wl0, wh1, wl1;
            split_pack(k4.x, k4.y, wh0, wl0);
            split_pack(k4.z, k4.w, wh1, wl1);
            Kh[r * A_PW + c4 * 2] = wh0; Kh[r * A_PW + c4 * 2 + 1] = wh1;
            Kl[r * A_PW + c4 * 2] = wl0; Kl[r * A_PW + c4 * 2 + 1] = wl1;
            int c = c4 * 4;
            Vs[r * A_PV + c]     = __uint_as_float(f2tf(v4.x));
            Vs[r * A_PV + c + 1] = __uint_as_float(f2tf(v4.y));
            Vs[r * A_PV + c + 2] = __uint_as_float(f2tf(v4.z));
            Vs[r * A_PV + c + 3] = __uint_as_float(f2tf(v4.w));
        }
        __syncthreads();

        // S = Q K^T, bf16x3 over 4 k16 chunks
        float s[8][4];
#pragma unroll
        for (int nc = 0; nc < 8; nc++)
#pragma unroll
            for (int e = 0; e < 4; e++) s[nc][e] = 0.0f;

#pragma unroll
        for (int kk = 0; kk < 4; kk++) {
            unsigned ah0, ah1, ah2, ah3, al0, al1, al2, al3;
            ldsm4(ah0, ah1, ah2, ah3, QhB + qAddr + kk * 32u);
            ldsm4(al0, al1, al2, al3, QlB + qAddr + kk * 32u);
#pragma unroll
            for (int p = 0; p < 4; p++) {
                unsigned kh0, kh1, kh2, kh3, kl0, kl1, kl2, kl3;
                ldsm4(kh0, kh1, kh2, kh3, KhB + kAddr[p] + kk * 32u);
                ldsm4(kl0, kl1, kl2, kl3, KlB + kAddr[p] + kk * 32u);
                mma16(s[2 * p],     ah0, ah1, ah2, ah3, kh0, kh1);
                mma16(s[2 * p],     al0, al1, al2, al3, kh0, kh1);
                mma16(s[2 * p],     ah0, ah1, ah2, ah3, kl0, kl1);
                mma16(s[2 * p + 1], ah0, ah1, ah2, ah3, kh2, kh3);
                mma16(s[2 * p + 1], al0, al1, al2, al3, kh2, kh3);
                mma16(s[2 * p + 1], ah0, ah1, ah2, ah3, kl2, kl3);
            }
        }

        // causal mask on diagonal tile
        if (j == qt) {
            int r0 = 16 * warp + (lane >> 2), r1 = r0 + 8;
#pragma unroll
            for (int nc = 0; nc < 8; nc++) {
                int c0 = nc * 8 + 2 * (lane & 3), c1 = c0 + 1;
                if (c0 > r0) s[nc][0] = NEG;
                if (c1 > r0) s[nc][1] = NEG;
                if (c0 > r1) s[nc][2] = NEG;
                if (c1 > r1) s[nc][3] = NEG;
            }
        }

        // online softmax
        float pm0 = NEG, pm1 = NEG;
#pragma unroll
        for (int nc = 0; nc < 8; nc++) {
            pm0 = fmaxf(pm0, fmaxf(s[nc][0], s[nc][1]));
            pm1 = fmaxf(pm1, fmaxf(s[nc][2], s[nc][3]));
        }
        pm0 = fmaxf(pm0, __shfl_xor_sync(0xffffffffu, pm0, 1));
        pm0 = fmaxf(pm0, __shfl_xor_sync(0xffffffffu, pm0, 2));
        pm1 = fmaxf(pm1, __shfl_xor_sync(0xffffffffu, pm1, 1));
        pm1 = fmaxf(pm1, __shfl_xor_sync(0xffffffffu, pm1, 2));

        float mn0 = fmaxf(mr0, pm0), mn1 = fmaxf(mr1, pm1);
        float al0 = __expf(mr0 - mn0), al1 = __expf(mr1 - mn1);
        l0 *= al0;
        l1 *= al1;

        float rs0 = 0.0f, rs1 = 0.0f;
        int pr0 = 16 * warp + (lane >> 2);
#pragma unroll
        for (int nc = 0; nc < 8; nc++) {
            float p0 = __expf(s[nc][0] - mn0);
            float p1 = __expf(s[nc][1] - mn0);
            float p2 = __expf(s[nc][2] - mn1);
            float p3 = __expf(s[nc][3] - mn1);
            rs0 += p0 + p1;
            rs1 += p2 + p3;
            o[nc][0] *= al0; o[nc][1] *= al0;
            o[nc][2] *= al1; o[nc][3] *= al1;
            int c0 = nc * 8 + 2 * (lane & 3);
            Ps[pr0 * A_PQ + c0]           = __uint_as_float(f2tf(p0));
            Ps[pr0 * A_PQ + c0 + 1]       = __uint_as_float(f2tf(p1));
            Ps[(pr0 + 8) * A_PQ + c0]     = __uint_as_float(f2tf(p2));
            Ps[(pr0 + 8) * A_PQ + c0 + 1] = __uint_as_float(f2tf(p3));
        }
        rs0 += __shfl_xor_sync(0xffffffffu, rs0, 1);
        rs0 += __shfl_xor_sync(0xffffffffu, rs0, 2);
        rs1 += __shfl_xor_sync(0xffffffffu, rs1, 1);
        rs1 += __shfl_xor_sync(0xffffffffu, rs1, 2);
        l0 += rs0;
        l1 += rs1;
        mr0 = mn0;
        mr1 = mn1;
        __syncwarp();   // P writes visible across lanes of this warp

        // O += P V  (TF32 k8, unchanged)
#pragma unroll
        for (int kk = 0; kk < 8; kk++) {
            int pb = (16 * warp + (lane >> 2)) * A_PQ + kk * 8 + (lane & 3);
            unsigned pa0 = fu(Ps[pb]), pa1 = fu(Ps[pb + 8 * A_PQ]);
            unsigned pa2 = fu(Ps[pb + 4]), pa3 = fu(Ps[pb + 8 * A_PQ + 4]);
#pragma unroll
            for (int nc = 0; nc < 8; nc++) {
                int vb = (kk * 8 + (lane & 3)) * A_PV + nc * 8 + (lane >> 2);
                unsigned v0 = fu(Vs[vb]), v1 = fu(Vs[vb + 4 * A_PV]);
                mma8(o[nc], pa0, pa1, pa2, pa3, v0, v1);
            }
        }
    }

    // epilogue
    float inv0 = 1.0f / l0, inv1 = 1.0f / l1;
    int r0g = q0 + 16 * warp + (lane >> 2);
    int r1g = r0g + 8;
#pragma unroll
    for (int nc = 0; nc < 8; nc++) {
        int col = h * HDIM + nc * 8 + 2 * (lane & 3);
        size_t b0 = ((size_t)(b * SEQ + r0g)) * DMODEL + col;
        size_t b1 = ((size_t)(b * SEQ + r1g)) * DMODEL + col;
        out[b0]     = o[nc][0] * inv0;
        out[b0 + 1] = o[nc][1] * inv0;
        out[b1]     = o[nc][2] * inv1;
        out[b1 + 1] = o[nc][3] * inv1;
    }
}

// ---------------------------------------------------------------------------
extern "C" void kernel_launch(void* const* d_in, const int* in_sizes, int n_in,
                              void* d_out, int out_size) {
    const float* x  = (const float*)d_in[0];
    const float* wq = (const float*)d_in[1];
    const float* wk = (const float*)d_in[2];
    const float* wv = (const float*)d_in[3];
    const float* wo = (const float*)d_in[4];

    float *gq, *gk, *gv, *gao;
    cudaGetSymbolAddress((void**)&gq, g_Q);
    cudaGetSymbolAddress((void**)&gk, g_K);
    cudaGetSymbolAddress((void**)&gv, g_V);
    cudaGetSymbolAddress((void**)&gao, g_AO);

    cudaFuncSetAttribute(proj_kernel, cudaFuncAttributeMaxDynamicSharedMemorySize,
                         PROJ_SMEM_BYTES);
    cudaFuncSetAttribute(attn_kernel, cudaFuncAttributeMaxDynamicSharedMemorySize,
                         ATTN_SMEM_BYTES);

    dim3 pgrid(MROWS / P_BM, DMODEL / P_BN);   // (64, 16)
    proj_kernel<<<pgrid, 256, PROJ_SMEM_BYTES>>>(x, wq, gq, 1);
    proj_kernel<<<pgrid, 256, PROJ_SMEM_BYTES>>>(x, wk, gk, 1);
    proj_kernel<<<pgrid, 256, PROJ_SMEM_BYTES>>>(x, wv, gv, 1);

    dim3 agrid(SEQ / 64, HEADS, BATCH);        // (32, 16, 4)
    attn_kernel<<<agrid, 128, ATTN_SMEM_BYTES>>>(gq, gk, gv, gao);

    proj_kernel<<<pgrid, 256, PROJ_SMEM_BYTES>>>(gao, wo, (float*)d_out, 0);
}